// round 15
// baseline (speedup 1.0000x reference)
#include <cuda_runtime.h>
#include <math.h>

// Problem constants
#define T_IN     65536
#define EDGE     27
#define TEXT     65590           // T_IN + 2*EDGE
#define NCH      512             // 32*16 channels
#define LBLK     256
#define NBLK     257             // ceil(65590/256); last block length 54
#define LAST_LEN 54
#define OUTT     16384           // T_IN/4
#define ORD      8

#define TOT_BLKTH (NCH*NBLK)     // 131584 = 1028*128
#define CHAIN_TH  (NBLK*8*NCH)   // 1052672 = 4112*256

// ---------------- device scratch (no allocations allowed) ----------------
// State arrays laid out [k][i][c]  (channel contiguous -> coalesced warps)
__device__ float  d_xt[(size_t)T_IN*NCH];  // transposed input  [t][c]
__device__ float  d_y [(size_t)TEXT*NCH];  // forward-true y    [t_ext][c]
__device__ float  d_Ff[NBLK*ORD*NCH];      // forward zero-state block-final states
__device__ float  d_Zf[NBLK*ORD*NCH];      // forward block-entry states (true)
__device__ float  d_Fb[NBLK*ORD*NCH];      // backward zero-state block-final states
__device__ float  d_Zb[NBLK*ORD*NCH];      // backward block-entry states (true)
__device__ float  d_yLast[NCH];            // TRUE forward y at last extended sample
__device__ float  d_b[9];
__device__ float  d_a[9];
__device__ double d_zid[8];
__device__ double d_Pd[4][64];             // (A^256)^m, m=0..3 (m=0 -> identity)
__device__ double d_Rd[4][64];             // (A^256)^m * A^54

// ---------------- setup: filter design + matrix tables (double) ----------------
__device__ inline void mm8(double dst[8][8], const double A_[8][8],
                           const double B_[8][8], int tid) {
    if (tid < 64) {
        int i = tid >> 3, j = tid & 7;
        double acc = 0.0;
#pragma unroll
        for (int t = 0; t < 8; t++) acc += A_[i][t] * B_[t][j];
        dst[i][j] = acc;
    }
}

__global__ void bd_setup_kernel() {
    __shared__ double sb[9], sa[9], szi[8];
    __shared__ double A[8][8];
    __shared__ double PW[9][8][8];
    __shared__ double T1[8][8], T2[8][8], M54[8][8], P2m[8][8], P3m[8][8];
    int tid = threadIdx.x;

    if (tid == 0) {
        const double PI = 3.14159265358979323846;
        // Chebyshev-I analog prototype, N=8, rp=0.05 dB
        double eps = sqrt(pow(10.0, 0.005) - 1.0);
        double mu  = asinh(1.0 / eps) / 8.0;
        double sm  = sinh(mu), cm = cosh(mu);
        double prr[8], pii[8];
        for (int k = 0; k < 8; k++) {
            double th = PI * (2.0 * (k + 1) - 1.0) / 16.0;
            prr[k] = -sm * sin(th);
            pii[k] =  cm * cos(th);
        }
        double gr = 1.0, gi = 0.0;
        for (int k = 0; k < 8; k++) {
            double xr = -prr[k], xi = -pii[k];
            double nr = gr * xr - gi * xi, ni = gr * xi + gi * xr;
            gr = nr; gi = ni;
        }
        double g = gr / sqrt(1.0 + eps * eps);
        double warped = 4.0 * tan(PI * 0.1);
        for (int k = 0; k < 8; k++) { prr[k] *= warped; pii[k] *= warped; }
        for (int i = 0; i < 8; i++) g *= warped;
        double pdr[8], pdi[8];
        double qr = 1.0, qi = 0.0;
        for (int k = 0; k < 8; k++) {
            double dr = 4.0 - prr[k], di = -pii[k];
            double nr = 4.0 + prr[k], ni =  pii[k];
            double d2 = dr * dr + di * di;
            pdr[k] = (nr * dr + ni * di) / d2;
            pdi[k] = (ni * dr - nr * di) / d2;
            double tr = qr * dr - qi * di, ti = qr * di + qi * dr;
            qr = tr; qi = ti;
        }
        double gd = g * qr / (qr * qr + qi * qi);
        double ac[9]; for (int j = 0; j < 9; j++) ac[j] = 0.0; ac[0] = 1.0;
        int deg = 0;
        for (int pp = 0; pp < 4; pp++) {
            double re = pdr[pp], im = pdi[pp];
            double c1 = -2.0 * re, c0 = re * re + im * im;
            double nc[9]; for (int j = 0; j < 9; j++) nc[j] = 0.0;
            for (int j = 0; j <= deg; j++) {
                nc[j]     += ac[j];
                nc[j + 1] += ac[j] * c1;
                nc[j + 2] += ac[j] * c0;
            }
            deg += 2;
            for (int j = 0; j < 9; j++) ac[j] = nc[j];
        }
        double binom[9] = {1, 8, 28, 56, 70, 56, 28, 8, 1};
        for (int j = 0; j < 9; j++) { sa[j] = ac[j]; sb[j] = gd * binom[j]; }
        // zi: solve (I - Comp^T) zi = b[1:] - a[1:]*b[0]
        double M[8][9];
        for (int i = 0; i < 8; i++)
            for (int j = 0; j < 9; j++) M[i][j] = 0.0;
        for (int i = 0; i < 8; i++) M[i][i] = 1.0;
        for (int i = 0; i < 8; i++) M[i][0] += sa[i + 1];
        for (int i = 0; i < 7; i++) M[i][i + 1] -= 1.0;
        for (int i = 0; i < 8; i++) M[i][8] = sb[i + 1] - sa[i + 1] * sb[0];
        for (int col = 0; col < 8; col++) {
            int piv = col;
            for (int r = col + 1; r < 8; r++)
                if (fabs(M[r][col]) > fabs(M[piv][col])) piv = r;
            if (piv != col)
                for (int j = 0; j < 9; j++) { double t = M[col][j]; M[col][j] = M[piv][j]; M[piv][j] = t; }
            double dv = M[col][col];
            for (int j = col; j < 9; j++) M[col][j] /= dv;
            for (int r = 0; r < 8; r++) {
                if (r == col) continue;
                double f = M[r][col];
                if (f != 0.0)
                    for (int j = col; j < 9; j++) M[r][j] -= f * M[col][j];
            }
        }
        for (int i = 0; i < 8; i++) szi[i] = M[i][8];
        for (int i = 0; i < 8; i++)
            for (int j = 0; j < 8; j++) A[i][j] = 0.0;
        for (int i = 0; i < 8; i++) A[i][0] = -sa[i + 1];
        for (int i = 0; i < 7; i++) A[i][i + 1] = 1.0;
        for (int j = 0; j < 9; j++) { d_b[j] = (float)sb[j]; d_a[j] = (float)sa[j]; }
        for (int j = 0; j < 8; j++) d_zid[j] = szi[j];
    }
    __syncthreads();

    if (tid < 64) PW[0][tid >> 3][tid & 7] = A[tid >> 3][tid & 7];
    __syncthreads();
    for (int s = 1; s < 9; s++) {            // PW[s] = A^(2^s)
        mm8(PW[s], PW[s - 1], PW[s - 1], tid);
        __syncthreads();
    }
    // A^54 = A^32 * A^16 * A^4 * A^2
    mm8(T1, PW[5], PW[4], tid); __syncthreads();
    mm8(T2, T1, PW[2], tid);    __syncthreads();
    mm8(M54, T2, PW[1], tid);   __syncthreads();
    mm8(P2m, PW[8], PW[8], tid); __syncthreads();
    mm8(P3m, P2m, PW[8], tid);   __syncthreads();

    if (tid < 64) {
        int i = tid >> 3, j = tid & 7;
        d_Pd[0][tid] = (i == j) ? 1.0 : 0.0;
        d_Pd[1][tid] = PW[8][i][j];
        d_Pd[2][tid] = P2m[i][j];
        d_Pd[3][tid] = P3m[i][j];
        d_Rd[0][tid] = M54[i][j];
    }
    __syncthreads();
    mm8(T1, PW[8], M54, tid); __syncthreads();
    if (tid < 64) d_Rd[1][tid] = T1[tid >> 3][tid & 7];
    __syncthreads();
    mm8(T1, P2m, M54, tid); __syncthreads();
    if (tid < 64) d_Rd[2][tid] = T1[tid >> 3][tid & 7];
    __syncthreads();
    mm8(T1, P3m, M54, tid); __syncthreads();
    if (tid < 64) d_Rd[3][tid] = T1[tid >> 3][tid & 7];
}

// ---------------- transpose: x[c][t] -> xt[t][c] ----------------
__global__ void bd_tr_kernel(const float* __restrict__ x) {
    __shared__ float tile[32][33];
    int t0 = blockIdx.x << 5, c0 = blockIdx.y << 5;
    int tx = threadIdx.x, ty = threadIdx.y;      // (32, 8)
#pragma unroll
    for (int j = 0; j < 32; j += 8)
        tile[ty + j][tx] = x[(size_t)(c0 + ty + j) * T_IN + t0 + tx];
    __syncthreads();
#pragma unroll
    for (int j = 0; j < 32; j += 8)
        d_xt[(size_t)(t0 + ty + j) * NCH + c0 + tx] = tile[tx][ty + j];
}

// ---------------- helpers ----------------
__device__ __forceinline__ float bd_ext_t(int t, int c) {
    if (t < EDGE) return 2.0f * d_xt[c] - d_xt[(size_t)(EDGE - t) * NCH + c];
    int u = t - EDGE;
    if (u < T_IN) return d_xt[(size_t)u * NCH + c];
    int j = u - T_IN;                       // 0..26
    return 2.0f * d_xt[(size_t)(T_IN - 1) * NCH + c]
               - d_xt[(size_t)(T_IN - 2 - j) * NCH + c];
}

__device__ __forceinline__ float bd_step(float s[8], const float rb[9],
                                         const float ra[8], float xv) {
    float y = fmaf(rb[0], xv, s[0]);
#pragma unroll
    for (int i = 0; i < 7; i++) {
        float t = fmaf(rb[i + 1], xv, s[i + 1]);
        s[i] = fmaf(-ra[i], y, t);
    }
    s[7] = fmaf(-ra[7], y, rb[8] * xv);
    return y;
}

// state array addressing: [k][i][c]
#define ST_IDX(k, i, c) (((size_t)(k) * ORD + (i)) * NCH + (c))

// ---------------- K1f: forward zero-state per block -> final states ----------------
__global__ void __launch_bounds__(128) bd_k1f_kernel() {
    int gid = blockIdx.x * blockDim.x + threadIdx.x;
    int c = gid & (NCH - 1);
    int k = gid >> 9;
    float rb[9], ra[8];
#pragma unroll
    for (int j = 0; j < 9; j++) rb[j] = d_b[j];
#pragma unroll
    for (int j = 0; j < 8; j++) ra[j] = d_a[j + 1];
    float s[8];
#pragma unroll
    for (int j = 0; j < 8; j++) s[j] = 0.0f;

    int t0 = k << 8;
    if (k >= 1 && k <= 255) {
        const float* p = d_xt + (size_t)(t0 - EDGE) * NCH + c;
        float buf[8], nbuf[8];
#pragma unroll
        for (int j = 0; j < 8; j++) buf[j] = p[(size_t)j * NCH];
        for (int i = 0; i < LBLK; i += 8) {
            if (i + 8 < LBLK) {
                const float* pn = p + (size_t)(i + 8) * NCH;
#pragma unroll
                for (int j = 0; j < 8; j++) nbuf[j] = pn[(size_t)j * NCH];
            }
#pragma unroll
            for (int j = 0; j < 8; j++) (void)bd_step(s, rb, ra, buf[j]);
#pragma unroll
            for (int j = 0; j < 8; j++) buf[j] = nbuf[j];
        }
    } else {
        int Lk = (k == NBLK - 1) ? LAST_LEN : LBLK;
        for (int i = 0; i < Lk; i++) (void)bd_step(s, rb, ra, bd_ext_t(t0 + i, c));
    }
#pragma unroll
    for (int j = 0; j < 8; j++) d_Ff[ST_IDX(k, j, c)] = s[j];
}

// ---------------- K2f: parallel truncated forward chain (fp64, row-parallel) ----------------
// one thread per (k, state-row i, channel c); coalesced F loads, uniform P rows
__global__ void bd_k2f_kernel(const float* __restrict__ x) {
    int gid = blockIdx.x * blockDim.x + threadIdx.x;
    if (gid >= CHAIN_TH) return;
    int c = gid & (NCH - 1);
    int i = (gid >> 9) & 7;
    int k = gid >> 12;

    double z = 0.0;
    if (k >= 1)                               // m = 0 term (P^0 = I)
        z = (double)d_Ff[ST_IDX(k - 1, i, c)];
#pragma unroll
    for (int m = 1; m < 4; m++) {
        int idx = k - 1 - m;
        if (idx >= 0) {
            const double* Pr = d_Pd[m] + i * 8;
            double acc = 0.0;
#pragma unroll
            for (int j = 0; j < 8; j++)
                acc += Pr[j] * (double)d_Ff[ST_IDX(idx, j, c)];
            z += acc;
        }
    }
    if (k <= 3) {                     // initial-state term (zi * ext0)
        const float* xc = x + (size_t)c * T_IN;
        double e0 = 2.0 * (double)xc[0] - (double)xc[EDGE];
        if (k == 0) {
            z += d_zid[i] * e0;
        } else {
            const double* Pr = d_Pd[k] + i * 8;
            double acc = 0.0;
#pragma unroll
            for (int j = 0; j < 8; j++) acc += Pr[j] * (d_zid[j] * e0);
            z += acc;
        }
    }
    d_Zf[ST_IDX(k, i, c)] = (float)z;
}

// ---------------- KA: fwd refilter (true state) -> y[t][c]; + zero-state backward ----------------
__global__ void __launch_bounds__(128) bd_kA_kernel() {
    int gid = blockIdx.x * blockDim.x + threadIdx.x;
    int c = gid & (NCH - 1);
    int k = gid >> 9;
    float rb[9], ra[8];
#pragma unroll
    for (int j = 0; j < 9; j++) rb[j] = d_b[j];
#pragma unroll
    for (int j = 0; j < 8; j++) ra[j] = d_a[j + 1];

    float s[8];
#pragma unroll
    for (int j = 0; j < 8; j++) s[j] = d_Zf[ST_IDX(k, j, c)];

    int t0 = k << 8;
    int Lk = (k == NBLK - 1) ? LAST_LEN : LBLK;
    float* yp = d_y + (size_t)t0 * NCH + c;

    if (k >= 1 && k <= 255) {
        const float* p = d_xt + (size_t)(t0 - EDGE) * NCH + c;
        float buf[8], nbuf[8];
#pragma unroll
        for (int j = 0; j < 8; j++) buf[j] = p[(size_t)j * NCH];
        for (int i = 0; i < LBLK; i += 8) {
            if (i + 8 < LBLK) {
                const float* pn = p + (size_t)(i + 8) * NCH;
#pragma unroll
                for (int j = 0; j < 8; j++) nbuf[j] = pn[(size_t)j * NCH];
            }
#pragma unroll
            for (int j = 0; j < 8; j++)
                yp[(size_t)(i + j) * NCH] = bd_step(s, rb, ra, buf[j]);
#pragma unroll
            for (int j = 0; j < 8; j++) buf[j] = nbuf[j];
        }
    } else {
        for (int i = 0; i < Lk; i++)
            yp[(size_t)i * NCH] = bd_step(s, rb, ra, bd_ext_t(t0 + i, c));
    }
    if (k == NBLK - 1) d_yLast[c] = yp[(size_t)(LAST_LEN - 1) * NCH];

    // backward zero-state over the just-written forward y (reverse order)
#pragma unroll
    for (int j = 0; j < 8; j++) s[j] = 0.0f;
    if (k <= 255) {
        float buf[8], nbuf[8];
#pragma unroll
        for (int j = 0; j < 8; j++) buf[j] = yp[(size_t)(LBLK - 1 - j) * NCH];
        for (int i = LBLK - 1; i >= 0; i -= 8) {
            if (i - 8 >= 0) {
#pragma unroll
                for (int j = 0; j < 8; j++) nbuf[j] = yp[(size_t)(i - 8 - j) * NCH];
            }
#pragma unroll
            for (int j = 0; j < 8; j++) (void)bd_step(s, rb, ra, buf[j]);
#pragma unroll
            for (int j = 0; j < 8; j++) buf[j] = nbuf[j];
        }
    } else {
        for (int i = Lk - 1; i >= 0; i--)
            (void)bd_step(s, rb, ra, yp[(size_t)i * NCH]);
    }

#pragma unroll
    for (int j = 0; j < 8; j++) d_Fb[ST_IDX(k, j, c)] = s[j];
}

// ---------------- K2b: parallel truncated backward chain (fp64, row-parallel) ----------------
__global__ void bd_k2b_kernel() {
    int gid = blockIdx.x * blockDim.x + threadIdx.x;
    if (gid >= CHAIN_TH) return;
    int c = gid & (NCH - 1);
    int i = (gid >> 9) & 7;
    int k = gid >> 12;

    double yl = (double)d_yLast[c];
    if (k == NBLK - 1) {
        d_Zb[ST_IDX(k, i, c)] = (float)(d_zid[i] * yl);
        return;
    }
    double z = 0.0;
    if (k + 1 <= 255)                         // m = 0 term (P^0 = I)
        z = (double)d_Fb[ST_IDX(k + 1, i, c)];
#pragma unroll
    for (int m = 1; m < 4; m++) {
        int jb = k + 1 + m;
        if (jb <= 255) {
            const double* Pr = d_Pd[m] + i * 8;
            double acc = 0.0;
#pragma unroll
            for (int j = 0; j < 8; j++)
                acc += Pr[j] * (double)d_Fb[ST_IDX(jb, j, c)];
            z += acc;
        }
    }
    int dlast = 255 - k;
    if (dlast <= 3) {                 // terms crossing the short last block
        const double* Pr = d_Pd[dlast] + i * 8;
        double acc = 0.0;
#pragma unroll
        for (int j = 0; j < 8; j++)
            acc += Pr[j] * (double)d_Fb[ST_IDX(NBLK - 1, j, c)];
        z += acc;
        const double* Rr = d_Rd[dlast] + i * 8;
        double acc2 = 0.0;
#pragma unroll
        for (int j = 0; j < 8; j++) acc2 += Rr[j] * (d_zid[j] * yl);
        z += acc2;
    }
    d_Zb[ST_IDX(k, i, c)] = (float)z;
}

// ---------------- KB: TRUE-state backward over stored y -> decimated outputs ----------------
__global__ void __launch_bounds__(128) bd_kB_kernel(float* __restrict__ out) {
    __shared__ float myo[128][65];          // padded: conflict-free both phases
    int tid = threadIdx.x;
    int gid = blockIdx.x * blockDim.x + tid;
    int c = gid & (NCH - 1);
    int k = gid >> 9;
    float rb[9], ra[8];
#pragma unroll
    for (int j = 0; j < 9; j++) rb[j] = d_b[j];
#pragma unroll
    for (int j = 0; j < 8; j++) ra[j] = d_a[j + 1];

    float s[8];
#pragma unroll
    for (int j = 0; j < 8; j++) s[j] = d_Zb[ST_IDX(k, j, c)];

    int t0 = k << 8;
    int Lk = (k == NBLK - 1) ? LAST_LEN : LBLK;
    int u0 = (k == 0) ? 0 : (t0 - 24);      // first decimated u in this block
    const float* yp = d_y + (size_t)t0 * NCH + c;

    if (k <= 255) {
        float buf[8], nbuf[8];
#pragma unroll
        for (int j = 0; j < 8; j++) buf[j] = yp[(size_t)(LBLK - 1 - j) * NCH];
        for (int i = LBLK - 1; i >= 0; i -= 8) {
            if (i - 8 >= 0) {
#pragma unroll
                for (int j = 0; j < 8; j++) nbuf[j] = yp[(size_t)(i - 8 - j) * NCH];
            }
#pragma unroll
            for (int j = 0; j < 8; j++) {
                float y = bd_step(s, rb, ra, buf[j]);
                int icur = i - j;
                int u = t0 + icur - EDGE;
                if (((icur & 3) == 3) && u >= 0 && u < T_IN)
                    myo[tid][(u - u0) >> 2] = y;
            }
#pragma unroll
            for (int j = 0; j < 8; j++) buf[j] = nbuf[j];
        }
    } else {
        for (int i = Lk - 1; i >= 0; i--) {
            float y = bd_step(s, rb, ra, yp[(size_t)i * NCH]);
            int u = t0 + i - EDGE;
            if (u >= 0 && u < T_IN && !(u & 3))
                myo[tid][(u - u0) >> 2] = y;
        }
    }
    __syncthreads();

    // coalesced output write: rows = 128 channels of this block, cols = decimated time
    int cnt = (k == 0) ? 58 : ((k == NBLK - 1) ? 6 : 64);
    int obase = u0 >> 2;
    int c0 = (blockIdx.x & 3) * 128;
    int wid = tid >> 5, lane = tid & 31;
    for (int r = wid; r < 128; r += 4)
        for (int o = lane; o < cnt; o += 32)
            out[(size_t)(c0 + r) * OUTT + obase + o] = myo[r][o];
}

// ---------------- launch ----------------
extern "C" void kernel_launch(void* const* d_in, const int* in_sizes, int n_in,
                              void* d_out, int out_size) {
    const float* x = (const float*)d_in[0];
    float* out = (float*)d_out;
    (void)in_sizes; (void)n_in; (void)out_size;

    bd_setup_kernel<<<1, 64>>>();
    bd_tr_kernel<<<dim3(T_IN / 32, NCH / 32), dim3(32, 8)>>>(x);
    bd_k1f_kernel<<<TOT_BLKTH / 128, 128>>>();
    bd_k2f_kernel<<<CHAIN_TH / 256, 256>>>(x);
    bd_kA_kernel<<<TOT_BLKTH / 128, 128>>>();
    bd_k2b_kernel<<<CHAIN_TH / 256, 256>>>();
    bd_kB_kernel<<<TOT_BLKTH / 128, 128>>>(out);
}

// round 16
// speedup vs baseline: 1.3556x; 1.3556x over previous
#include <cuda_runtime.h>
#include <math.h>

// Problem constants
#define T_IN     65536
#define EDGE     27
#define TEXT     65590           // T_IN + 2*EDGE
#define NCH      512             // 32*16 channels
#define LBLK     256
#define NBLK     257             // ceil(65590/256); last block length 54
#define LAST_LEN 54
#define OUTT     16384           // T_IN/4
#define ORD      8

#define TOT_BLKTH (NCH*NBLK)     // 131584 = 1028*128
#define CHAIN_TH  (NBLK*8*NCH)   // 1052672 = 4112*256

// ---------------- device scratch (no allocations allowed) ----------------
// State arrays laid out [k][i][c]  (channel contiguous -> coalesced warps)
__device__ float  d_xt[(size_t)T_IN*NCH];  // transposed input  [t][c]
__device__ float  d_y [(size_t)TEXT*NCH];  // forward-true y    [t_ext][c]
__device__ float  d_Ff[NBLK*ORD*NCH];      // forward zero-state block-final states
__device__ float  d_Zf[NBLK*ORD*NCH];      // forward block-entry states (true)
__device__ float  d_Fb[NBLK*ORD*NCH];      // backward zero-state block-final states
__device__ float  d_Zb[NBLK*ORD*NCH];      // backward block-entry states (true)
__device__ float  d_yLast[NCH];            // TRUE forward y at last extended sample
__device__ float  d_b[9];
__device__ float  d_a[9];
__device__ float2 d_zi2[8];                // zi as double-float (hi, lo)
__device__ float2 d_P2[4][64];             // (A^256)^m as double-float, m=0..3
__device__ float2 d_R2[4][64];             // (A^256)^m * A^54 as double-float

// ---------------- setup: filter design + matrix tables (double) ----------------
__device__ inline void mm8(double dst[8][8], const double A_[8][8],
                           const double B_[8][8], int tid) {
    if (tid < 64) {
        int i = tid >> 3, j = tid & 7;
        double acc = 0.0;
#pragma unroll
        for (int t = 0; t < 8; t++) acc += A_[i][t] * B_[t][j];
        dst[i][j] = acc;
    }
}

__device__ __forceinline__ float2 dbl_to_df(double v) {
    float hi = (float)v;
    float lo = (float)(v - (double)hi);
    return make_float2(hi, lo);
}

__global__ void bd_setup_kernel() {
    __shared__ double sb[9], sa[9], szi[8];
    __shared__ double A[8][8];
    __shared__ double PW[9][8][8];
    __shared__ double T1[8][8], T2[8][8], M54[8][8], P2m[8][8], P3m[8][8];
    int tid = threadIdx.x;

    if (tid == 0) {
        const double PI = 3.14159265358979323846;
        // Chebyshev-I analog prototype, N=8, rp=0.05 dB
        double eps = sqrt(pow(10.0, 0.005) - 1.0);
        double mu  = asinh(1.0 / eps) / 8.0;
        double sm  = sinh(mu), cm = cosh(mu);
        double prr[8], pii[8];
        for (int k = 0; k < 8; k++) {
            double th = PI * (2.0 * (k + 1) - 1.0) / 16.0;
            prr[k] = -sm * sin(th);
            pii[k] =  cm * cos(th);
        }
        double gr = 1.0, gi = 0.0;
        for (int k = 0; k < 8; k++) {
            double xr = -prr[k], xi = -pii[k];
            double nr = gr * xr - gi * xi, ni = gr * xi + gi * xr;
            gr = nr; gi = ni;
        }
        double g = gr / sqrt(1.0 + eps * eps);
        double warped = 4.0 * tan(PI * 0.1);
        for (int k = 0; k < 8; k++) { prr[k] *= warped; pii[k] *= warped; }
        for (int i = 0; i < 8; i++) g *= warped;
        double pdr[8], pdi[8];
        double qr = 1.0, qi = 0.0;
        for (int k = 0; k < 8; k++) {
            double dr = 4.0 - prr[k], di = -pii[k];
            double nr = 4.0 + prr[k], ni =  pii[k];
            double d2 = dr * dr + di * di;
            pdr[k] = (nr * dr + ni * di) / d2;
            pdi[k] = (ni * dr - nr * di) / d2;
            double tr = qr * dr - qi * di, ti = qr * di + qi * dr;
            qr = tr; qi = ti;
        }
        double gd = g * qr / (qr * qr + qi * qi);
        double ac[9]; for (int j = 0; j < 9; j++) ac[j] = 0.0; ac[0] = 1.0;
        int deg = 0;
        for (int pp = 0; pp < 4; pp++) {
            double re = pdr[pp], im = pdi[pp];
            double c1 = -2.0 * re, c0 = re * re + im * im;
            double nc[9]; for (int j = 0; j < 9; j++) nc[j] = 0.0;
            for (int j = 0; j <= deg; j++) {
                nc[j]     += ac[j];
                nc[j + 1] += ac[j] * c1;
                nc[j + 2] += ac[j] * c0;
            }
            deg += 2;
            for (int j = 0; j < 9; j++) ac[j] = nc[j];
        }
        double binom[9] = {1, 8, 28, 56, 70, 56, 28, 8, 1};
        for (int j = 0; j < 9; j++) { sa[j] = ac[j]; sb[j] = gd * binom[j]; }
        // zi: solve (I - Comp^T) zi = b[1:] - a[1:]*b[0]
        double M[8][9];
        for (int i = 0; i < 8; i++)
            for (int j = 0; j < 9; j++) M[i][j] = 0.0;
        for (int i = 0; i < 8; i++) M[i][i] = 1.0;
        for (int i = 0; i < 8; i++) M[i][0] += sa[i + 1];
        for (int i = 0; i < 7; i++) M[i][i + 1] -= 1.0;
        for (int i = 0; i < 8; i++) M[i][8] = sb[i + 1] - sa[i + 1] * sb[0];
        for (int col = 0; col < 8; col++) {
            int piv = col;
            for (int r = col + 1; r < 8; r++)
                if (fabs(M[r][col]) > fabs(M[piv][col])) piv = r;
            if (piv != col)
                for (int j = 0; j < 9; j++) { double t = M[col][j]; M[col][j] = M[piv][j]; M[piv][j] = t; }
            double dv = M[col][col];
            for (int j = col; j < 9; j++) M[col][j] /= dv;
            for (int r = 0; r < 8; r++) {
                if (r == col) continue;
                double f = M[r][col];
                if (f != 0.0)
                    for (int j = col; j < 9; j++) M[r][j] -= f * M[col][j];
            }
        }
        for (int i = 0; i < 8; i++) szi[i] = M[i][8];
        for (int i = 0; i < 8; i++)
            for (int j = 0; j < 8; j++) A[i][j] = 0.0;
        for (int i = 0; i < 8; i++) A[i][0] = -sa[i + 1];
        for (int i = 0; i < 7; i++) A[i][i + 1] = 1.0;
        for (int j = 0; j < 9; j++) { d_b[j] = (float)sb[j]; d_a[j] = (float)sa[j]; }
        for (int j = 0; j < 8; j++) d_zi2[j] = dbl_to_df(szi[j]);
    }
    __syncthreads();

    if (tid < 64) PW[0][tid >> 3][tid & 7] = A[tid >> 3][tid & 7];
    __syncthreads();
    for (int s = 1; s < 9; s++) {            // PW[s] = A^(2^s)
        mm8(PW[s], PW[s - 1], PW[s - 1], tid);
        __syncthreads();
    }
    // A^54 = A^32 * A^16 * A^4 * A^2
    mm8(T1, PW[5], PW[4], tid); __syncthreads();
    mm8(T2, T1, PW[2], tid);    __syncthreads();
    mm8(M54, T2, PW[1], tid);   __syncthreads();
    mm8(P2m, PW[8], PW[8], tid); __syncthreads();
    mm8(P3m, P2m, PW[8], tid);   __syncthreads();

    if (tid < 64) {
        int i = tid >> 3, j = tid & 7;
        d_P2[0][tid] = make_float2((i == j) ? 1.0f : 0.0f, 0.0f);
        d_P2[1][tid] = dbl_to_df(PW[8][i][j]);
        d_P2[2][tid] = dbl_to_df(P2m[i][j]);
        d_P2[3][tid] = dbl_to_df(P3m[i][j]);
        d_R2[0][tid] = dbl_to_df(M54[i][j]);
    }
    __syncthreads();
    mm8(T1, PW[8], M54, tid); __syncthreads();
    if (tid < 64) d_R2[1][tid] = dbl_to_df(T1[tid >> 3][tid & 7]);
    __syncthreads();
    mm8(T1, P2m, M54, tid); __syncthreads();
    if (tid < 64) d_R2[2][tid] = dbl_to_df(T1[tid >> 3][tid & 7]);
    __syncthreads();
    mm8(T1, P3m, M54, tid); __syncthreads();
    if (tid < 64) d_R2[3][tid] = dbl_to_df(T1[tid >> 3][tid & 7]);
}

// ---------------- double-float helpers (fp32 pipe) ----------------
// TwoSum + renormalize
__device__ __forceinline__ float2 df_add(float2 a, float2 b) {
    float s = a.x + b.x;
    float v = s - a.x;
    float e = (a.x - (s - v)) + (b.x - v);
    e += a.y + b.y;
    float hi = s + e;
    float lo = e - (hi - s);
    return make_float2(hi, lo);
}
// (hi,lo) matrix element times exact fp32 value -> df (TwoProd via FMA)
__device__ __forceinline__ float2 df_mulf(float2 P, float f) {
    float p = P.x * f;
    float e = fmaf(P.x, f, -p);
    e = fmaf(P.y, f, e);
    return make_float2(p, e);
}
// (hi,lo) matrix element times df value -> df (drops P.y*v.y term ~2^-48)
__device__ __forceinline__ float2 df_muldf(float2 P, float2 v) {
    float p = P.x * v.x;
    float e = fmaf(P.x, v.x, -p);
    e = fmaf(P.y, v.x, e);
    e = fmaf(P.x, v.y, e);
    return make_float2(p, e);
}
// exact two_sum of two floats
__device__ __forceinline__ float2 two_sum(float a, float b) {
    float s = a + b;
    float v = s - a;
    float e = (a - (s - v)) + (b - v);
    return make_float2(s, e);
}

// ---------------- transpose: x[c][t] -> xt[t][c] ----------------
__global__ void bd_tr_kernel(const float* __restrict__ x) {
    __shared__ float tile[32][33];
    int t0 = blockIdx.x << 5, c0 = blockIdx.y << 5;
    int tx = threadIdx.x, ty = threadIdx.y;      // (32, 8)
#pragma unroll
    for (int j = 0; j < 32; j += 8)
        tile[ty + j][tx] = x[(size_t)(c0 + ty + j) * T_IN + t0 + tx];
    __syncthreads();
#pragma unroll
    for (int j = 0; j < 32; j += 8)
        d_xt[(size_t)(t0 + ty + j) * NCH + c0 + tx] = tile[tx][ty + j];
}

// ---------------- helpers ----------------
__device__ __forceinline__ float bd_ext_t(int t, int c) {
    if (t < EDGE) return 2.0f * d_xt[c] - d_xt[(size_t)(EDGE - t) * NCH + c];
    int u = t - EDGE;
    if (u < T_IN) return d_xt[(size_t)u * NCH + c];
    int j = u - T_IN;                       // 0..26
    return 2.0f * d_xt[(size_t)(T_IN - 1) * NCH + c]
               - d_xt[(size_t)(T_IN - 2 - j) * NCH + c];
}

__device__ __forceinline__ float bd_step(float s[8], const float rb[9],
                                         const float ra[8], float xv) {
    float y = fmaf(rb[0], xv, s[0]);
#pragma unroll
    for (int i = 0; i < 7; i++) {
        float t = fmaf(rb[i + 1], xv, s[i + 1]);
        s[i] = fmaf(-ra[i], y, t);
    }
    s[7] = fmaf(-ra[7], y, rb[8] * xv);
    return y;
}

// state array addressing: [k][i][c]
#define ST_IDX(k, i, c) (((size_t)(k) * ORD + (i)) * NCH + (c))

// ---------------- K1f: forward zero-state per block -> final states ----------------
__global__ void __launch_bounds__(128) bd_k1f_kernel() {
    int gid = blockIdx.x * blockDim.x + threadIdx.x;
    int c = gid & (NCH - 1);
    int k = gid >> 9;
    float rb[9], ra[8];
#pragma unroll
    for (int j = 0; j < 9; j++) rb[j] = d_b[j];
#pragma unroll
    for (int j = 0; j < 8; j++) ra[j] = d_a[j + 1];
    float s[8];
#pragma unroll
    for (int j = 0; j < 8; j++) s[j] = 0.0f;

    int t0 = k << 8;
    if (k >= 1 && k <= 255) {
        const float* p = d_xt + (size_t)(t0 - EDGE) * NCH + c;
        float buf[8], nbuf[8];
#pragma unroll
        for (int j = 0; j < 8; j++) buf[j] = p[(size_t)j * NCH];
        for (int i = 0; i < LBLK; i += 8) {
            if (i + 8 < LBLK) {
                const float* pn = p + (size_t)(i + 8) * NCH;
#pragma unroll
                for (int j = 0; j < 8; j++) nbuf[j] = pn[(size_t)j * NCH];
            }
#pragma unroll
            for (int j = 0; j < 8; j++) (void)bd_step(s, rb, ra, buf[j]);
#pragma unroll
            for (int j = 0; j < 8; j++) buf[j] = nbuf[j];
        }
    } else {
        int Lk = (k == NBLK - 1) ? LAST_LEN : LBLK;
        for (int i = 0; i < Lk; i++) (void)bd_step(s, rb, ra, bd_ext_t(t0 + i, c));
    }
#pragma unroll
    for (int j = 0; j < 8; j++) d_Ff[ST_IDX(k, j, c)] = s[j];
}

// ---------------- K2f: parallel truncated forward chain (double-float, row-parallel) ----------------
__global__ void bd_k2f_kernel(const float* __restrict__ x) {
    int gid = blockIdx.x * blockDim.x + threadIdx.x;
    if (gid >= CHAIN_TH) return;
    int c = gid & (NCH - 1);
    int i = (gid >> 9) & 7;
    int k = gid >> 12;

    float2 z = make_float2(0.0f, 0.0f);
    if (k >= 1)                               // m = 0 term (P^0 = I)
        z = make_float2(d_Ff[ST_IDX(k - 1, i, c)], 0.0f);
#pragma unroll
    for (int m = 1; m < 4; m++) {
        int idx = k - 1 - m;
        if (idx >= 0) {
            const float2* Pr = d_P2[m] + i * 8;
#pragma unroll
            for (int j = 0; j < 8; j++)
                z = df_add(z, df_mulf(Pr[j], d_Ff[ST_IDX(idx, j, c)]));
        }
    }
    if (k <= 3) {                     // initial-state term (zi * ext0)
        const float* xc = x + (size_t)c * T_IN;
        float2 e0 = two_sum(2.0f * xc[0], -xc[EDGE]);
        if (k == 0) {
            z = df_add(z, df_muldf(d_zi2[i], e0));
        } else {
            const float2* Pr = d_P2[k] + i * 8;
#pragma unroll
            for (int j = 0; j < 8; j++)
                z = df_add(z, df_muldf(Pr[j], df_muldf(d_zi2[j], e0)));
        }
    }
    d_Zf[ST_IDX(k, i, c)] = z.x + z.y;
}

// ---------------- KA: fwd refilter (true state) -> y[t][c]; + zero-state backward ----------------
__global__ void __launch_bounds__(128) bd_kA_kernel() {
    int gid = blockIdx.x * blockDim.x + threadIdx.x;
    int c = gid & (NCH - 1);
    int k = gid >> 9;
    float rb[9], ra[8];
#pragma unroll
    for (int j = 0; j < 9; j++) rb[j] = d_b[j];
#pragma unroll
    for (int j = 0; j < 8; j++) ra[j] = d_a[j + 1];

    float s[8];
#pragma unroll
    for (int j = 0; j < 8; j++) s[j] = d_Zf[ST_IDX(k, j, c)];

    int t0 = k << 8;
    int Lk = (k == NBLK - 1) ? LAST_LEN : LBLK;
    float* yp = d_y + (size_t)t0 * NCH + c;

    if (k >= 1 && k <= 255) {
        const float* p = d_xt + (size_t)(t0 - EDGE) * NCH + c;
        float buf[8], nbuf[8];
#pragma unroll
        for (int j = 0; j < 8; j++) buf[j] = p[(size_t)j * NCH];
        for (int i = 0; i < LBLK; i += 8) {
            if (i + 8 < LBLK) {
                const float* pn = p + (size_t)(i + 8) * NCH;
#pragma unroll
                for (int j = 0; j < 8; j++) nbuf[j] = pn[(size_t)j * NCH];
            }
#pragma unroll
            for (int j = 0; j < 8; j++)
                yp[(size_t)(i + j) * NCH] = bd_step(s, rb, ra, buf[j]);
#pragma unroll
            for (int j = 0; j < 8; j++) buf[j] = nbuf[j];
        }
    } else {
        for (int i = 0; i < Lk; i++)
            yp[(size_t)i * NCH] = bd_step(s, rb, ra, bd_ext_t(t0 + i, c));
    }
    if (k == NBLK - 1) d_yLast[c] = yp[(size_t)(LAST_LEN - 1) * NCH];

    // backward zero-state over the just-written forward y (reverse order)
#pragma unroll
    for (int j = 0; j < 8; j++) s[j] = 0.0f;
    if (k <= 255) {
        float buf[8], nbuf[8];
#pragma unroll
        for (int j = 0; j < 8; j++) buf[j] = yp[(size_t)(LBLK - 1 - j) * NCH];
        for (int i = LBLK - 1; i >= 0; i -= 8) {
            if (i - 8 >= 0) {
#pragma unroll
                for (int j = 0; j < 8; j++) nbuf[j] = yp[(size_t)(i - 8 - j) * NCH];
            }
#pragma unroll
            for (int j = 0; j < 8; j++) (void)bd_step(s, rb, ra, buf[j]);
#pragma unroll
            for (int j = 0; j < 8; j++) buf[j] = nbuf[j];
        }
    } else {
        for (int i = Lk - 1; i >= 0; i--)
            (void)bd_step(s, rb, ra, yp[(size_t)i * NCH]);
    }

#pragma unroll
    for (int j = 0; j < 8; j++) d_Fb[ST_IDX(k, j, c)] = s[j];
}

// ---------------- K2b: parallel truncated backward chain (double-float, row-parallel) ----------------
__global__ void bd_k2b_kernel() {
    int gid = blockIdx.x * blockDim.x + threadIdx.x;
    if (gid >= CHAIN_TH) return;
    int c = gid & (NCH - 1);
    int i = (gid >> 9) & 7;
    int k = gid >> 12;

    float yl = d_yLast[c];
    if (k == NBLK - 1) {
        float2 v = df_mulf(d_zi2[i], yl);
        d_Zb[ST_IDX(k, i, c)] = v.x + v.y;
        return;
    }
    float2 z = make_float2(0.0f, 0.0f);
    if (k + 1 <= 255)                         // m = 0 term (P^0 = I)
        z = make_float2(d_Fb[ST_IDX(k + 1, i, c)], 0.0f);
#pragma unroll
    for (int m = 1; m < 4; m++) {
        int jb = k + 1 + m;
        if (jb <= 255) {
            const float2* Pr = d_P2[m] + i * 8;
#pragma unroll
            for (int j = 0; j < 8; j++)
                z = df_add(z, df_mulf(Pr[j], d_Fb[ST_IDX(jb, j, c)]));
        }
    }
    int dlast = 255 - k;
    if (dlast <= 3) {                 // terms crossing the short last block
        const float2* Pr = d_P2[dlast] + i * 8;
#pragma unroll
        for (int j = 0; j < 8; j++)
            z = df_add(z, df_mulf(Pr[j], d_Fb[ST_IDX(NBLK - 1, j, c)]));
        const float2* Rr = d_R2[dlast] + i * 8;
#pragma unroll
        for (int j = 0; j < 8; j++)
            z = df_add(z, df_muldf(Rr[j], df_mulf(d_zi2[j], yl)));
    }
    d_Zb[ST_IDX(k, i, c)] = z.x + z.y;
}

// ---------------- KB: TRUE-state backward over stored y -> decimated outputs ----------------
__global__ void __launch_bounds__(128) bd_kB_kernel(float* __restrict__ out) {
    __shared__ float myo[128][65];          // padded: conflict-free both phases
    int tid = threadIdx.x;
    int gid = blockIdx.x * blockDim.x + tid;
    int c = gid & (NCH - 1);
    int k = gid >> 9;
    float rb[9], ra[8];
#pragma unroll
    for (int j = 0; j < 9; j++) rb[j] = d_b[j];
#pragma unroll
    for (int j = 0; j < 8; j++) ra[j] = d_a[j + 1];

    float s[8];
#pragma unroll
    for (int j = 0; j < 8; j++) s[j] = d_Zb[ST_IDX(k, j, c)];

    int t0 = k << 8;
    int Lk = (k == NBLK - 1) ? LAST_LEN : LBLK;
    int u0 = (k == 0) ? 0 : (t0 - 24);      // first decimated u in this block
    const float* yp = d_y + (size_t)t0 * NCH + c;

    if (k <= 255) {
        float buf[8], nbuf[8];
#pragma unroll
        for (int j = 0; j < 8; j++) buf[j] = yp[(size_t)(LBLK - 1 - j) * NCH];
        for (int i = LBLK - 1; i >= 0; i -= 8) {
            if (i - 8 >= 0) {
#pragma unroll
                for (int j = 0; j < 8; j++) nbuf[j] = yp[(size_t)(i - 8 - j) * NCH];
            }
#pragma unroll
            for (int j = 0; j < 8; j++) {
                float y = bd_step(s, rb, ra, buf[j]);
                int icur = i - j;
                int u = t0 + icur - EDGE;
                if (((icur & 3) == 3) && u >= 0 && u < T_IN)
                    myo[tid][(u - u0) >> 2] = y;
            }
#pragma unroll
            for (int j = 0; j < 8; j++) buf[j] = nbuf[j];
        }
    } else {
        for (int i = Lk - 1; i >= 0; i--) {
            float y = bd_step(s, rb, ra, yp[(size_t)i * NCH]);
            int u = t0 + i - EDGE;
            if (u >= 0 && u < T_IN && !(u & 3))
                myo[tid][(u - u0) >> 2] = y;
        }
    }
    __syncthreads();

    // coalesced output write: rows = 128 channels of this block, cols = decimated time
    int cnt = (k == 0) ? 58 : ((k == NBLK - 1) ? 6 : 64);
    int obase = u0 >> 2;
    int c0 = (blockIdx.x & 3) * 128;
    int wid = tid >> 5, lane = tid & 31;
    for (int r = wid; r < 128; r += 4)
        for (int o = lane; o < cnt; o += 32)
            out[(size_t)(c0 + r) * OUTT + obase + o] = myo[r][o];
}

// ---------------- launch ----------------
extern "C" void kernel_launch(void* const* d_in, const int* in_sizes, int n_in,
                              void* d_out, int out_size) {
    const float* x = (const float*)d_in[0];
    float* out = (float*)d_out;
    (void)in_sizes; (void)n_in; (void)out_size;

    bd_setup_kernel<<<1, 64>>>();
    bd_tr_kernel<<<dim3(T_IN / 32, NCH / 32), dim3(32, 8)>>>(x);
    bd_k1f_kernel<<<TOT_BLKTH / 128, 128>>>();
    bd_k2f_kernel<<<CHAIN_TH / 256, 256>>>(x);
    bd_kA_kernel<<<TOT_BLKTH / 128, 128>>>();
    bd_k2b_kernel<<<CHAIN_TH / 256, 256>>>();
    bd_kB_kernel<<<TOT_BLKTH / 128, 128>>>(out);
}

// round 17
// speedup vs baseline: 1.3601x; 1.0033x over previous
#include <cuda_runtime.h>
#include <math.h>

// Problem constants
#define T_IN     65536
#define EDGE     27
#define TEXT     65590           // T_IN + 2*EDGE
#define NCH      512             // 32*16 channels
#define LBLK     256
#define NBLK     257             // ceil(65590/256); last block length 54
#define LAST_LEN 54
#define OUTT     16384           // T_IN/4
#define ORD      8

#define TOT_BLKTH (NCH*NBLK)     // 131584 = 1028*128
#define CHAIN_TH  (NBLK*8*NCH)   // 1052672 = 4112*256

// ---------------- device scratch (no allocations allowed) ----------------
// State arrays laid out [k][i][c]  (channel contiguous -> coalesced warps)
__device__ float  d_xt[(size_t)T_IN*NCH];  // transposed input  [t][c]
__device__ float  d_y [(size_t)TEXT*NCH];  // forward-true y    [t_ext][c]
__device__ float  d_Ff[NBLK*ORD*NCH];      // forward zero-state block-final states
__device__ float  d_Zf[NBLK*ORD*NCH];      // forward block-entry states (true)
__device__ float  d_Fb[NBLK*ORD*NCH];      // backward zero-state block-final states
__device__ float  d_Zb[NBLK*ORD*NCH];      // backward block-entry states (true)
__device__ float  d_yLast[NCH];            // TRUE forward y at last extended sample
__device__ float  d_b[9];
__device__ float  d_a[9];
__device__ float2 d_zi2[8];                // zi as double-float (hi, lo)
__device__ float2 d_P2[4][64];             // (A^256)^m as double-float, m=0..3
__device__ float2 d_R2[4][64];             // (A^256)^m * A^54 as double-float

// ---------------- setup: filter design + matrix tables (double) ----------------
__device__ inline void mm8(double dst[8][8], const double A_[8][8],
                           const double B_[8][8], int tid) {
    if (tid < 64) {
        int i = tid >> 3, j = tid & 7;
        double acc = 0.0;
#pragma unroll
        for (int t = 0; t < 8; t++) acc += A_[i][t] * B_[t][j];
        dst[i][j] = acc;
    }
}

__device__ __forceinline__ float2 dbl_to_df(double v) {
    float hi = (float)v;
    float lo = (float)(v - (double)hi);
    return make_float2(hi, lo);
}

__global__ void bd_setup_kernel() {
    __shared__ double sb[9], sa[9], szi[8];
    __shared__ double A[8][8];
    __shared__ double PW[9][8][8];
    __shared__ double T1[8][8], T2[8][8], M54[8][8], P2m[8][8], P3m[8][8];
    int tid = threadIdx.x;

    if (tid == 0) {
        const double PI = 3.14159265358979323846;
        // Chebyshev-I analog prototype, N=8, rp=0.05 dB
        double eps = sqrt(pow(10.0, 0.005) - 1.0);
        double mu  = asinh(1.0 / eps) / 8.0;
        double sm  = sinh(mu), cm = cosh(mu);
        double prr[8], pii[8];
        for (int k = 0; k < 8; k++) {
            double th = PI * (2.0 * (k + 1) - 1.0) / 16.0;
            prr[k] = -sm * sin(th);
            pii[k] =  cm * cos(th);
        }
        double gr = 1.0, gi = 0.0;
        for (int k = 0; k < 8; k++) {
            double xr = -prr[k], xi = -pii[k];
            double nr = gr * xr - gi * xi, ni = gr * xi + gi * xr;
            gr = nr; gi = ni;
        }
        double g = gr / sqrt(1.0 + eps * eps);
        double warped = 4.0 * tan(PI * 0.1);
        for (int k = 0; k < 8; k++) { prr[k] *= warped; pii[k] *= warped; }
        for (int i = 0; i < 8; i++) g *= warped;
        double pdr[8], pdi[8];
        double qr = 1.0, qi = 0.0;
        for (int k = 0; k < 8; k++) {
            double dr = 4.0 - prr[k], di = -pii[k];
            double nr = 4.0 + prr[k], ni =  pii[k];
            double d2 = dr * dr + di * di;
            pdr[k] = (nr * dr + ni * di) / d2;
            pdi[k] = (ni * dr - nr * di) / d2;
            double tr = qr * dr - qi * di, ti = qr * di + qi * dr;
            qr = tr; qi = ti;
        }
        double gd = g * qr / (qr * qr + qi * qi);
        double ac[9]; for (int j = 0; j < 9; j++) ac[j] = 0.0; ac[0] = 1.0;
        int deg = 0;
        for (int pp = 0; pp < 4; pp++) {
            double re = pdr[pp], im = pdi[pp];
            double c1 = -2.0 * re, c0 = re * re + im * im;
            double nc[9]; for (int j = 0; j < 9; j++) nc[j] = 0.0;
            for (int j = 0; j <= deg; j++) {
                nc[j]     += ac[j];
                nc[j + 1] += ac[j] * c1;
                nc[j + 2] += ac[j] * c0;
            }
            deg += 2;
            for (int j = 0; j < 9; j++) ac[j] = nc[j];
        }
        double binom[9] = {1, 8, 28, 56, 70, 56, 28, 8, 1};
        for (int j = 0; j < 9; j++) { sa[j] = ac[j]; sb[j] = gd * binom[j]; }
        // zi: solve (I - Comp^T) zi = b[1:] - a[1:]*b[0]
        double M[8][9];
        for (int i = 0; i < 8; i++)
            for (int j = 0; j < 9; j++) M[i][j] = 0.0;
        for (int i = 0; i < 8; i++) M[i][i] = 1.0;
        for (int i = 0; i < 8; i++) M[i][0] += sa[i + 1];
        for (int i = 0; i < 7; i++) M[i][i + 1] -= 1.0;
        for (int i = 0; i < 8; i++) M[i][8] = sb[i + 1] - sa[i + 1] * sb[0];
        for (int col = 0; col < 8; col++) {
            int piv = col;
            for (int r = col + 1; r < 8; r++)
                if (fabs(M[r][col]) > fabs(M[piv][col])) piv = r;
            if (piv != col)
                for (int j = 0; j < 9; j++) { double t = M[col][j]; M[col][j] = M[piv][j]; M[piv][j] = t; }
            double dv = M[col][col];
            for (int j = col; j < 9; j++) M[col][j] /= dv;
            for (int r = 0; r < 8; r++) {
                if (r == col) continue;
                double f = M[r][col];
                if (f != 0.0)
                    for (int j = col; j < 9; j++) M[r][j] -= f * M[col][j];
            }
        }
        for (int i = 0; i < 8; i++) szi[i] = M[i][8];
        for (int i = 0; i < 8; i++)
            for (int j = 0; j < 8; j++) A[i][j] = 0.0;
        for (int i = 0; i < 8; i++) A[i][0] = -sa[i + 1];
        for (int i = 0; i < 7; i++) A[i][i + 1] = 1.0;
        for (int j = 0; j < 9; j++) { d_b[j] = (float)sb[j]; d_a[j] = (float)sa[j]; }
        for (int j = 0; j < 8; j++) d_zi2[j] = dbl_to_df(szi[j]);
    }
    __syncthreads();

    if (tid < 64) PW[0][tid >> 3][tid & 7] = A[tid >> 3][tid & 7];
    __syncthreads();
    for (int s = 1; s < 9; s++) {            // PW[s] = A^(2^s)
        mm8(PW[s], PW[s - 1], PW[s - 1], tid);
        __syncthreads();
    }
    // A^54 = A^32 * A^16 * A^4 * A^2
    mm8(T1, PW[5], PW[4], tid); __syncthreads();
    mm8(T2, T1, PW[2], tid);    __syncthreads();
    mm8(M54, T2, PW[1], tid);   __syncthreads();
    mm8(P2m, PW[8], PW[8], tid); __syncthreads();
    mm8(P3m, P2m, PW[8], tid);   __syncthreads();

    if (tid < 64) {
        int i = tid >> 3, j = tid & 7;
        d_P2[0][tid] = make_float2((i == j) ? 1.0f : 0.0f, 0.0f);
        d_P2[1][tid] = dbl_to_df(PW[8][i][j]);
        d_P2[2][tid] = dbl_to_df(P2m[i][j]);
        d_P2[3][tid] = dbl_to_df(P3m[i][j]);
        d_R2[0][tid] = dbl_to_df(M54[i][j]);
    }
    __syncthreads();
    mm8(T1, PW[8], M54, tid); __syncthreads();
    if (tid < 64) d_R2[1][tid] = dbl_to_df(T1[tid >> 3][tid & 7]);
    __syncthreads();
    mm8(T1, P2m, M54, tid); __syncthreads();
    if (tid < 64) d_R2[2][tid] = dbl_to_df(T1[tid >> 3][tid & 7]);
    __syncthreads();
    mm8(T1, P3m, M54, tid); __syncthreads();
    if (tid < 64) d_R2[3][tid] = dbl_to_df(T1[tid >> 3][tid & 7]);
}

// ---------------- double-float helpers (fp32 pipe) ----------------
// TwoSum + renormalize
__device__ __forceinline__ float2 df_add(float2 a, float2 b) {
    float s = a.x + b.x;
    float v = s - a.x;
    float e = (a.x - (s - v)) + (b.x - v);
    e += a.y + b.y;
    float hi = s + e;
    float lo = e - (hi - s);
    return make_float2(hi, lo);
}
// (hi,lo) matrix element times exact fp32 value -> df (TwoProd via FMA)
__device__ __forceinline__ float2 df_mulf(float2 P, float f) {
    float p = P.x * f;
    float e = fmaf(P.x, f, -p);
    e = fmaf(P.y, f, e);
    return make_float2(p, e);
}
// (hi,lo) matrix element times df value -> df (drops P.y*v.y term ~2^-48)
__device__ __forceinline__ float2 df_muldf(float2 P, float2 v) {
    float p = P.x * v.x;
    float e = fmaf(P.x, v.x, -p);
    e = fmaf(P.y, v.x, e);
    e = fmaf(P.x, v.y, e);
    return make_float2(p, e);
}
// exact two_sum of two floats
__device__ __forceinline__ float2 two_sum(float a, float b) {
    float s = a + b;
    float v = s - a;
    float e = (a - (s - v)) + (b - v);
    return make_float2(s, e);
}

// ---------------- transpose: x[c][t] -> xt[t][c] ----------------
__global__ void bd_tr_kernel(const float* __restrict__ x) {
    __shared__ float tile[32][33];
    int t0 = blockIdx.x << 5, c0 = blockIdx.y << 5;
    int tx = threadIdx.x, ty = threadIdx.y;      // (32, 8)
#pragma unroll
    for (int j = 0; j < 32; j += 8)
        tile[ty + j][tx] = x[(size_t)(c0 + ty + j) * T_IN + t0 + tx];
    __syncthreads();
#pragma unroll
    for (int j = 0; j < 32; j += 8)
        d_xt[(size_t)(t0 + ty + j) * NCH + c0 + tx] = tile[tx][ty + j];
}

// ---------------- helpers ----------------
__device__ __forceinline__ float bd_ext_t(int t, int c) {
    if (t < EDGE) return 2.0f * d_xt[c] - d_xt[(size_t)(EDGE - t) * NCH + c];
    int u = t - EDGE;
    if (u < T_IN) return d_xt[(size_t)u * NCH + c];
    int j = u - T_IN;                       // 0..26
    return 2.0f * d_xt[(size_t)(T_IN - 1) * NCH + c]
               - d_xt[(size_t)(T_IN - 2 - j) * NCH + c];
}

__device__ __forceinline__ float bd_step(float s[8], const float rb[9],
                                         const float ra[8], float xv) {
    float y = fmaf(rb[0], xv, s[0]);
#pragma unroll
    for (int i = 0; i < 7; i++) {
        float t = fmaf(rb[i + 1], xv, s[i + 1]);
        s[i] = fmaf(-ra[i], y, t);
    }
    s[7] = fmaf(-ra[7], y, rb[8] * xv);
    return y;
}

// state array addressing: [k][i][c]
#define ST_IDX(k, i, c) (((size_t)(k) * ORD + (i)) * NCH + (c))

// ---------------- K1f: forward zero-state per block -> final states ----------------
__global__ void __launch_bounds__(128) bd_k1f_kernel() {
    int gid = blockIdx.x * blockDim.x + threadIdx.x;
    int c = gid & (NCH - 1);
    int k = gid >> 9;
    float rb[9], ra[8];
#pragma unroll
    for (int j = 0; j < 9; j++) rb[j] = d_b[j];
#pragma unroll
    for (int j = 0; j < 8; j++) ra[j] = d_a[j + 1];
    float s[8];
#pragma unroll
    for (int j = 0; j < 8; j++) s[j] = 0.0f;

    int t0 = k << 8;
    if (k >= 1 && k <= 255) {
        const float* p = d_xt + (size_t)(t0 - EDGE) * NCH + c;
        float buf[8], nbuf[8];
#pragma unroll
        for (int j = 0; j < 8; j++) buf[j] = p[(size_t)j * NCH];
        for (int i = 0; i < LBLK; i += 8) {
            if (i + 8 < LBLK) {
                const float* pn = p + (size_t)(i + 8) * NCH;
#pragma unroll
                for (int j = 0; j < 8; j++) nbuf[j] = pn[(size_t)j * NCH];
            }
#pragma unroll
            for (int j = 0; j < 8; j++) (void)bd_step(s, rb, ra, buf[j]);
#pragma unroll
            for (int j = 0; j < 8; j++) buf[j] = nbuf[j];
        }
    } else {
        int Lk = (k == NBLK - 1) ? LAST_LEN : LBLK;
        for (int i = 0; i < Lk; i++) (void)bd_step(s, rb, ra, bd_ext_t(t0 + i, c));
    }
#pragma unroll
    for (int j = 0; j < 8; j++) d_Ff[ST_IDX(k, j, c)] = s[j];
}

// ---------------- K2f: parallel truncated forward chain (double-float, row-parallel) ----------------
__global__ void bd_k2f_kernel(const float* __restrict__ x) {
    int gid = blockIdx.x * blockDim.x + threadIdx.x;
    if (gid >= CHAIN_TH) return;
    int c = gid & (NCH - 1);
    int i = (gid >> 9) & 7;
    int k = gid >> 12;

    float2 z = make_float2(0.0f, 0.0f);
    if (k >= 1)                               // m = 0 term (P^0 = I)
        z = make_float2(d_Ff[ST_IDX(k - 1, i, c)], 0.0f);
#pragma unroll
    for (int m = 1; m < 4; m++) {
        int idx = k - 1 - m;
        if (idx >= 0) {
            const float2* Pr = d_P2[m] + i * 8;
#pragma unroll
            for (int j = 0; j < 8; j++)
                z = df_add(z, df_mulf(Pr[j], d_Ff[ST_IDX(idx, j, c)]));
        }
    }
    if (k <= 3) {                     // initial-state term (zi * ext0)
        const float* xc = x + (size_t)c * T_IN;
        float2 e0 = two_sum(2.0f * xc[0], -xc[EDGE]);
        if (k == 0) {
            z = df_add(z, df_muldf(d_zi2[i], e0));
        } else {
            const float2* Pr = d_P2[k] + i * 8;
#pragma unroll
            for (int j = 0; j < 8; j++)
                z = df_add(z, df_muldf(Pr[j], df_muldf(d_zi2[j], e0)));
        }
    }
    d_Zf[ST_IDX(k, i, c)] = z.x + z.y;
}

// ---------------- KA: fwd refilter (true state) -> y[t][c]; + zero-state backward ----------------
__global__ void __launch_bounds__(128) bd_kA_kernel() {
    int gid = blockIdx.x * blockDim.x + threadIdx.x;
    int c = gid & (NCH - 1);
    int k = gid >> 9;
    float rb[9], ra[8];
#pragma unroll
    for (int j = 0; j < 9; j++) rb[j] = d_b[j];
#pragma unroll
    for (int j = 0; j < 8; j++) ra[j] = d_a[j + 1];

    float s[8];
#pragma unroll
    for (int j = 0; j < 8; j++) s[j] = d_Zf[ST_IDX(k, j, c)];

    int t0 = k << 8;
    int Lk = (k == NBLK - 1) ? LAST_LEN : LBLK;
    float* yp = d_y + (size_t)t0 * NCH + c;

    if (k >= 1 && k <= 255) {
        const float* p = d_xt + (size_t)(t0 - EDGE) * NCH + c;
        float buf[8], nbuf[8];
#pragma unroll
        for (int j = 0; j < 8; j++) buf[j] = p[(size_t)j * NCH];
        for (int i = 0; i < LBLK; i += 8) {
            if (i + 8 < LBLK) {
                const float* pn = p + (size_t)(i + 8) * NCH;
#pragma unroll
                for (int j = 0; j < 8; j++) nbuf[j] = pn[(size_t)j * NCH];
            }
#pragma unroll
            for (int j = 0; j < 8; j++)
                yp[(size_t)(i + j) * NCH] = bd_step(s, rb, ra, buf[j]);
#pragma unroll
            for (int j = 0; j < 8; j++) buf[j] = nbuf[j];
        }
    } else {
        for (int i = 0; i < Lk; i++)
            yp[(size_t)i * NCH] = bd_step(s, rb, ra, bd_ext_t(t0 + i, c));
    }
    if (k == NBLK - 1) d_yLast[c] = yp[(size_t)(LAST_LEN - 1) * NCH];

    // backward zero-state over the just-written forward y (reverse order)
#pragma unroll
    for (int j = 0; j < 8; j++) s[j] = 0.0f;
    if (k <= 255) {
        float buf[8], nbuf[8];
#pragma unroll
        for (int j = 0; j < 8; j++) buf[j] = yp[(size_t)(LBLK - 1 - j) * NCH];
        for (int i = LBLK - 1; i >= 0; i -= 8) {
            if (i - 8 >= 0) {
#pragma unroll
                for (int j = 0; j < 8; j++) nbuf[j] = yp[(size_t)(i - 8 - j) * NCH];
            }
#pragma unroll
            for (int j = 0; j < 8; j++) (void)bd_step(s, rb, ra, buf[j]);
#pragma unroll
            for (int j = 0; j < 8; j++) buf[j] = nbuf[j];
        }
    } else {
        for (int i = Lk - 1; i >= 0; i--)
            (void)bd_step(s, rb, ra, yp[(size_t)i * NCH]);
    }

#pragma unroll
    for (int j = 0; j < 8; j++) d_Fb[ST_IDX(k, j, c)] = s[j];
}

// ---------------- K2b: parallel truncated backward chain (double-float, row-parallel) ----------------
__global__ void bd_k2b_kernel() {
    int gid = blockIdx.x * blockDim.x + threadIdx.x;
    if (gid >= CHAIN_TH) return;
    int c = gid & (NCH - 1);
    int i = (gid >> 9) & 7;
    int k = gid >> 12;

    float yl = d_yLast[c];
    if (k == NBLK - 1) {
        float2 v = df_mulf(d_zi2[i], yl);
        d_Zb[ST_IDX(k, i, c)] = v.x + v.y;
        return;
    }
    float2 z = make_float2(0.0f, 0.0f);
    if (k + 1 <= 255)                         // m = 0 term (P^0 = I)
        z = make_float2(d_Fb[ST_IDX(k + 1, i, c)], 0.0f);
#pragma unroll
    for (int m = 1; m < 4; m++) {
        int jb = k + 1 + m;
        if (jb <= 255) {
            const float2* Pr = d_P2[m] + i * 8;
#pragma unroll
            for (int j = 0; j < 8; j++)
                z = df_add(z, df_mulf(Pr[j], d_Fb[ST_IDX(jb, j, c)]));
        }
    }
    int dlast = 255 - k;
    if (dlast <= 3) {                 // terms crossing the short last block
        const float2* Pr = d_P2[dlast] + i * 8;
#pragma unroll
        for (int j = 0; j < 8; j++)
            z = df_add(z, df_mulf(Pr[j], d_Fb[ST_IDX(NBLK - 1, j, c)]));
        const float2* Rr = d_R2[dlast] + i * 8;
#pragma unroll
        for (int j = 0; j < 8; j++)
            z = df_add(z, df_muldf(Rr[j], df_mulf(d_zi2[j], yl)));
    }
    d_Zb[ST_IDX(k, i, c)] = z.x + z.y;
}

// ---------------- KB: TRUE-state backward over stored y -> decimated outputs ----------------
__global__ void __launch_bounds__(128) bd_kB_kernel(float* __restrict__ out) {
    __shared__ float myo[128][65];          // padded: conflict-free both phases
    int tid = threadIdx.x;
    int gid = blockIdx.x * blockDim.x + tid;
    int c = gid & (NCH - 1);
    int k = gid >> 9;
    float rb[9], ra[8];
#pragma unroll
    for (int j = 0; j < 9; j++) rb[j] = d_b[j];
#pragma unroll
    for (int j = 0; j < 8; j++) ra[j] = d_a[j + 1];

    float s[8];
#pragma unroll
    for (int j = 0; j < 8; j++) s[j] = d_Zb[ST_IDX(k, j, c)];

    int t0 = k << 8;
    int Lk = (k == NBLK - 1) ? LAST_LEN : LBLK;
    int u0 = (k == 0) ? 0 : (t0 - 24);      // first decimated u in this block
    const float* yp = d_y + (size_t)t0 * NCH + c;

    if (k <= 255) {
        float buf[8], nbuf[8];
#pragma unroll
        for (int j = 0; j < 8; j++) buf[j] = yp[(size_t)(LBLK - 1 - j) * NCH];
        for (int i = LBLK - 1; i >= 0; i -= 8) {
            if (i - 8 >= 0) {
#pragma unroll
                for (int j = 0; j < 8; j++) nbuf[j] = yp[(size_t)(i - 8 - j) * NCH];
            }
#pragma unroll
            for (int j = 0; j < 8; j++) {
                float y = bd_step(s, rb, ra, buf[j]);
                int icur = i - j;
                int u = t0 + icur - EDGE;
                if (((icur & 3) == 3) && u >= 0 && u < T_IN)
                    myo[tid][(u - u0) >> 2] = y;
            }
#pragma unroll
            for (int j = 0; j < 8; j++) buf[j] = nbuf[j];
        }
    } else {
        for (int i = Lk - 1; i >= 0; i--) {
            float y = bd_step(s, rb, ra, yp[(size_t)i * NCH]);
            int u = t0 + i - EDGE;
            if (u >= 0 && u < T_IN && !(u & 3))
                myo[tid][(u - u0) >> 2] = y;
        }
    }
    __syncthreads();

    // coalesced output write: rows = 128 channels of this block, cols = decimated time
    int cnt = (k == 0) ? 58 : ((k == NBLK - 1) ? 6 : 64);
    int obase = u0 >> 2;
    int c0 = (blockIdx.x & 3) * 128;
    int wid = tid >> 5, lane = tid & 31;
    for (int r = wid; r < 128; r += 4)
        for (int o = lane; o < cnt; o += 32)
            out[(size_t)(c0 + r) * OUTT + obase + o] = myo[r][o];
}

// ---------------- launch ----------------
extern "C" void kernel_launch(void* const* d_in, const int* in_sizes, int n_in,
                              void* d_out, int out_size) {
    const float* x = (const float*)d_in[0];
    float* out = (float*)d_out;
    (void)in_sizes; (void)n_in; (void)out_size;

    bd_setup_kernel<<<1, 64>>>();
    bd_tr_kernel<<<dim3(T_IN / 32, NCH / 32), dim3(32, 8)>>>(x);
    bd_k1f_kernel<<<TOT_BLKTH / 128, 128>>>();
    bd_k2f_kernel<<<CHAIN_TH / 256, 256>>>(x);
    bd_kA_kernel<<<TOT_BLKTH / 128, 128>>>();
    bd_k2b_kernel<<<CHAIN_TH / 256, 256>>>();
    bd_kB_kernel<<<TOT_BLKTH / 128, 128>>>(out);
}